// round 15
// baseline (speedup 1.0000x reference)
#include <cuda_runtime.h>
#include <cuda_bf16.h>
#include <mma.h>
#include <cstdint>

using namespace nvcuda;

#define DIMN 1024
#define SEQ 50
#define BATCH 512
#define HEADS 16
#define HD 64
#define ROWS (BATCH*SEQ)   /* 25600 */
#define LN_EPS 1e-5f

// ---------------- scratch (device globals; no allocation allowed) -------------
__device__ __nv_bfloat16 g_ln[3ull * ROWS * DIMN];    // normalized Q,K,V (bf16)
__device__ __nv_bfloat16 g_proj[3ull * ROWS * DIMN];  // projected q,k,v (bf16)
__device__ __nv_bfloat16 g_ctx[(size_t)ROWS * DIMN];  // attention context (bf16)
__device__ __nv_bfloat16 g_wbf[4ull * DIMN * DIMN];   // bf16 weights

// ---------------- cp.async helpers -------------------------------------------
__device__ __forceinline__ uint32_t smem_u32(const void* p) {
    uint32_t a;
    asm("{ .reg .u64 t; cvta.to.shared.u64 t, %1; cvt.u32.u64 %0, t; }" : "=r"(a) : "l"(p));
    return a;
}
#define CP_ASYNC16(dst, src) \
    asm volatile("cp.async.ca.shared.global [%0], [%1], 16;" :: "r"(dst), "l"(src))
#define CP_COMMIT() asm volatile("cp.async.commit_group;" ::: "memory")
#define CP_WAIT1()  asm volatile("cp.async.wait_group 1;" ::: "memory")
#define CP_WAIT0()  asm volatile("cp.async.wait_group 0;" ::: "memory")

// ---------------- prep: LayerNorm (bf16 out) + weight conversion ---------------
// blocks [0, 3*ROWS): LN of Q/K/V rows.  blocks [3*ROWS, 3*ROWS+4096): W->bf16.
__global__ __launch_bounds__(256) void prep_kernel(
    const float* __restrict__ Q, const float* __restrict__ K,
    const float* __restrict__ V, const float* __restrict__ gamma,
    const float* __restrict__ beta, __nv_bfloat16* __restrict__ out,
    const float* __restrict__ Wq, const float* __restrict__ Wk,
    const float* __restrict__ Wv, const float* __restrict__ Wo,
    __nv_bfloat16* __restrict__ wbf)
{
    int blk = blockIdx.x;
    int tid = threadIdx.x;

    if (blk >= 3 * ROWS) {
        // ---- weight conversion: 4096 blocks, 1024 fp32 each ----
        int cb = blk - 3 * ROWS;
        int w  = cb >> 10;                       // 0..3
        const float* src = (w == 0) ? Wq : (w == 1) ? Wk : (w == 2) ? Wv : Wo;
        __nv_bfloat16* dst = wbf + (size_t)w * DIMN * DIMN;
        size_t i = ((size_t)(cb & 1023) * 256 + tid) * 4;
        float4 v = *(const float4*)(src + i);
        __nv_bfloat162 p0 = {__float2bfloat16(v.x), __float2bfloat16(v.y)};
        __nv_bfloat162 p1 = {__float2bfloat16(v.z), __float2bfloat16(v.w)};
        *(__nv_bfloat162*)(dst + i)     = p0;
        *(__nv_bfloat162*)(dst + i + 2) = p1;
        return;
    }

    // ---- LayerNorm: one block per row ----
    int row = blk;
    const float* src;
    if (row < ROWS)            src = Q + (size_t)row * DIMN;
    else if (row < 2 * ROWS)   src = K + (size_t)(row - ROWS) * DIMN;
    else                       src = V + (size_t)(row - 2 * ROWS) * DIMN;
    __nv_bfloat16* dst = out + (size_t)row * DIMN;

    float4 x = *(const float4*)(src + tid * 4);
    float s = x.x + x.y + x.z + x.w;
    float q = x.x * x.x + x.y * x.y + x.z * x.z + x.w * x.w;

    __shared__ float red[2][8];
    #pragma unroll
    for (int o = 16; o; o >>= 1) {
        s += __shfl_xor_sync(0xffffffffu, s, o);
        q += __shfl_xor_sync(0xffffffffu, q, o);
    }
    int warp = tid >> 5, lane = tid & 31;
    if (lane == 0) { red[0][warp] = s; red[1][warp] = q; }
    __syncthreads();
    if (warp == 0) {
        s = (lane < 8) ? red[0][lane] : 0.f;
        q = (lane < 8) ? red[1][lane] : 0.f;
        #pragma unroll
        for (int o = 4; o; o >>= 1) {
            s += __shfl_xor_sync(0xffffffffu, s, o);
            q += __shfl_xor_sync(0xffffffffu, q, o);
        }
        if (lane == 0) { red[0][0] = s; red[1][0] = q; }
    }
    __syncthreads();
    float mean = red[0][0] * (1.0f / DIMN);
    float var  = red[1][0] * (1.0f / DIMN) - mean * mean;
    float inv  = rsqrtf(var + LN_EPS);

    float4 g4 = *(const float4*)(gamma + tid * 4);
    float4 b4 = *(const float4*)(beta + tid * 4);
    __nv_bfloat162 p0 = {__float2bfloat16((x.x - mean) * inv * g4.x + b4.x),
                         __float2bfloat16((x.y - mean) * inv * g4.y + b4.y)};
    __nv_bfloat162 p1 = {__float2bfloat16((x.z - mean) * inv * g4.z + b4.z),
                         __float2bfloat16((x.w - mean) * inv * g4.w + b4.w)};
    *(__nv_bfloat162*)(dst + tid * 4)     = p0;
    *(__nv_bfloat162*)(dst + tid * 4 + 2) = p1;
}

// ---------------- bf16 wmma GEMM: 128x128 block, 3-stage, 2 CTAs/SM ------------
// C[M,N] = A[M,K] @ W[K,N] + bias (+resid). A,W bf16; accum fp32.
// 8 warps, warp tile 64x32 (4x2 frags). ONE __syncthreads per K-chunk.
#define BM 128
#define BN 128
#define BK 64
#define APAD 72    // A row stride (bf16): 144B
#define BPAD 136   // B row stride (bf16): 272B
#define STG_H (BM*APAD + BK*BPAD)          /* 9216+8704 = 17920 bf16 = 35840 B */
#define NSTG 3
#define GEMM_SMEM ((NSTG*STG_H*2) > (BM*BN*4) ? (NSTG*STG_H*2) : (BM*BN*4))  /* 107520 */
#define NKT (DIMN/BK)                      /* 16 */

template<bool BF16OUT>
__global__ __launch_bounds__(256, 2) void gemm_bf16(
    const __nv_bfloat16* __restrict__ A0, const __nv_bfloat16* __restrict__ W0,
    const float* __restrict__ b0, const float* __restrict__ b1,
    const float* __restrict__ b2,
    const float* __restrict__ resid,
    float* __restrict__ Cf, __nv_bfloat16* __restrict__ Cb)
{
    extern __shared__ char smraw[];
    __nv_bfloat16* sm = (__nv_bfloat16*)smraw;
    int tid  = threadIdx.x;
    int warp = tid >> 5;
    int wr   = warp >> 2;                  // 0..1 -> M offset wr*64
    int wc   = warp & 3;                   // 0..3 -> N offset wc*32

    int z = blockIdx.z;
    size_t seg  = (size_t)ROWS * DIMN;
    size_t wseg = (size_t)DIMN * DIMN;
    const __nv_bfloat16* A = A0 + z * seg;
    const __nv_bfloat16* W = W0 + z * wseg;
    const float* bias = (z == 0) ? b0 : ((z == 1) ? b1 : b2);

    size_t m0 = (size_t)blockIdx.y * BM;
    int n0 = blockIdx.x * BN;
    const __nv_bfloat16* Ag = A + m0 * DIMN;
    const __nv_bfloat16* Wg = W + n0;

    wmma::fragment<wmma::accumulator, 16, 16, 16, float> cf[4][2];
    #pragma unroll
    for (int i = 0; i < 4; i++)
        #pragma unroll
        for (int j = 0; j < 2; j++)
            wmma::fill_fragment(cf[i][j], 0.0f);

    auto load_stage = [&](int kt, int s) {
        __nv_bfloat16* As = sm + s * STG_H;
        __nv_bfloat16* Bs = As + BM * APAD;
        #pragma unroll
        for (int it = 0; it < 4; it++) {          // A: 128 rows x 8 chunks of 8 bf16
            int i = tid + it * 256;
            int r = i >> 3, c8 = i & 7;
            CP_ASYNC16(smem_u32(As + r * APAD + c8 * 8),
                       Ag + (size_t)r * DIMN + kt * BK + c8 * 8);
        }
        #pragma unroll
        for (int it = 0; it < 4; it++) {          // B: 64 rows x 16 chunks of 8 bf16
            int i = tid + it * 256;
            int r = i >> 4, c8 = i & 15;
            CP_ASYNC16(smem_u32(Bs + r * BPAD + c8 * 8),
                       Wg + (size_t)(kt * BK + r) * DIMN + c8 * 8);
        }
        CP_COMMIT();
    };

    load_stage(0, 0);
    load_stage(1, 1);

    for (int kt = 0; kt < NKT; kt++) {
        int s = kt % NSTG;
        if (kt + 1 < NKT) { CP_WAIT1(); } else { CP_WAIT0(); }
        __syncthreads();
        // Safe: this sync also proves all warps finished compute on stage
        // (kt+2)%3 (== stage of kt-1's target), so the new load can't race.
        if (kt + 2 < NKT) load_stage(kt + 2, (kt + 2) % NSTG);

        const __nv_bfloat16* As = sm + s * STG_H;
        const __nv_bfloat16* Bs = As + BM * APAD;
        #pragma unroll
        for (int ks = 0; ks < 4; ks++) {          // 4 x k16 per chunk
            wmma::fragment<wmma::matrix_a, 16, 16, 16, __nv_bfloat16, wmma::row_major> af[4];
            wmma::fragment<wmma::matrix_b, 16, 16, 16, __nv_bfloat16, wmma::row_major> bf[2];
            #pragma unroll
            for (int i = 0; i < 4; i++)
                wmma::load_matrix_sync(af[i], As + (wr * 64 + i * 16) * APAD + ks * 16, APAD);
            #pragma unroll
            for (int j = 0; j < 2; j++)
                wmma::load_matrix_sync(bf[j], Bs + (ks * 16) * BPAD + wc * 32 + j * 16, BPAD);
            #pragma unroll
            for (int i = 0; i < 4; i++)
                #pragma unroll
                for (int j = 0; j < 2; j++)
                    wmma::mma_sync(cf[i][j], af[i], bf[j], cf[i][j]);
        }
    }
    __syncthreads();

    // ---- epilogue: stage C tile in smem (fp32), add bias, write ----
    float* Cs = (float*)smraw;   // 128*128*4 = 64KB
    #pragma unroll
    for (int i = 0; i < 4; i++)
        #pragma unroll
        for (int j = 0; j < 2; j++)
            wmma::store_matrix_sync(Cs + (wr * 64 + i * 16) * BN + wc * 32 + j * 16,
                                    cf[i][j], BN, wmma::mem_row_major);
    __syncthreads();

    #pragma unroll
    for (int it = 0; it < 16; it++) {             // 128*128/4/256 = 16
        int i = tid + it * 256;
        int r = i >> 5;
        int c4 = (i & 31) * 4;
        float4 acc = *(float4*)(Cs + r * BN + c4);
        float4 bv  = *(const float4*)(bias + n0 + c4);
        acc.x += bv.x; acc.y += bv.y; acc.z += bv.z; acc.w += bv.w;
        if (BF16OUT) {
            __nv_bfloat16* dst = Cb + z * seg + (m0 + r) * DIMN + n0 + c4;
            __nv_bfloat162 p0 = {__float2bfloat16(acc.x), __float2bfloat16(acc.y)};
            __nv_bfloat162 p1 = {__float2bfloat16(acc.z), __float2bfloat16(acc.w)};
            *(__nv_bfloat162*)(dst)     = p0;
            *(__nv_bfloat162*)(dst + 2) = p1;
        } else {
            float4 rv = *(const float4*)(resid + (m0 + r) * DIMN + n0 + c4);
            acc.x += rv.x; acc.y += rv.y; acc.z += rv.z; acc.w += rv.w;
            *(float4*)(Cf + (m0 + r) * DIMN + n0 + c4) = acc;
        }
    }
}

// ---------------- Attention: one block per (batch, head); bf16 in/out ----------
// mask is int32 (bool promoted): nonzero => masked (-inf)
__global__ __launch_bounds__(256) void attn_kernel(
    const __nv_bfloat16* __restrict__ qp, const __nv_bfloat16* __restrict__ kp,
    const __nv_bfloat16* __restrict__ vp, const int* __restrict__ mask,
    __nv_bfloat16* __restrict__ ctx)
{
    int h = blockIdx.x;
    int b = blockIdx.y;
    __shared__ float sq[SEQ * 64];
    __shared__ float sk[SEQ * 65];
    __shared__ float sv[SEQ * 64];
    __shared__ float sp[SEQ * 51];

    int tid = threadIdx.x;
    size_t base = ((size_t)b * SEQ) * DIMN + h * HD;
    for (int idx = tid; idx < SEQ * 64; idx += 256) {
        int s = idx >> 6, d = idx & 63;
        size_t g = base + (size_t)s * DIMN + d;
        sq[idx]        = __bfloat162float(qp[g]);
        sk[s * 65 + d] = __bfloat162float(kp[g]);
        sv[idx]        = __bfloat162float(vp[g]);
    }
    __syncthreads();

    int warp = tid >> 5, lane = tid & 31;
    int rows[7];
    int nr = 0;
    #pragma unroll
    for (int t = 0; t < 7; t++) {
        int r = warp + 8 * t;
        if (r < SEQ) { rows[t] = r; nr = t + 1; }
        else rows[t] = SEQ - 1;
    }

    const int* mrow = mask + (size_t)b * SEQ * SEQ;
    int j0 = lane;
    int j1c = (lane + 32 < SEQ) ? (lane + 32) : (SEQ - 1);
    bool j1ok = (lane + 32) < SEQ;

    float a0[7], a1[7];
    #pragma unroll
    for (int t = 0; t < 7; t++) { a0[t] = 0.f; a1[t] = 0.f; }
    for (int d = 0; d < 64; d++) {
        float k0 = sk[j0 * 65 + d];
        float k1 = sk[j1c * 65 + d];
        #pragma unroll
        for (int t = 0; t < 7; t++) {
            float qv = sq[rows[t] * 64 + d];
            a0[t] = fmaf(qv, k0, a0[t]);
            a1[t] = fmaf(qv, k1, a1[t]);
        }
    }
    const float NEGINF = __int_as_float(0xff800000);
    #pragma unroll
    for (int t = 0; t < 7; t++) {
        int r = rows[t];
        a0[t] *= 0.125f;
        a1[t] *= 0.125f;
        if (mrow[r * SEQ + j0]) a0[t] = NEGINF;
        if (!j1ok || mrow[r * SEQ + j1c]) a1[t] = NEGINF;
    }

    #pragma unroll
    for (int t = 0; t < 7; t++) {
        float m = fmaxf(a0[t], a1[t]);
        #pragma unroll
        for (int o = 16; o; o >>= 1) m = fmaxf(m, __shfl_xor_sync(0xffffffffu, m, o));
        float e0 = __expf(a0[t] - m);
        float e1 = __expf(a1[t] - m);
        float ss = e0 + e1;
        #pragma unroll
        for (int o = 16; o; o >>= 1) ss += __shfl_xor_sync(0xffffffffu, ss, o);
        float inv = 1.0f / ss;
        if (t < nr) {
            sp[rows[t] * 51 + j0] = e0 * inv;
            if (j1ok) sp[rows[t] * 51 + lane + 32] = e1 * inv;
        }
    }
    __syncthreads();

    float c0[7], c1[7];
    #pragma unroll
    for (int t = 0; t < 7; t++) { c0[t] = 0.f; c1[t] = 0.f; }
    for (int j = 0; j < SEQ; j++) {
        float v0 = sv[j * 64 + lane];
        float v1 = sv[j * 64 + lane + 32];
        #pragma unroll
        for (int t = 0; t < 7; t++) {
            float pj = sp[rows[t] * 51 + j];
            c0[t] = fmaf(pj, v0, c0[t]);
            c1[t] = fmaf(pj, v1, c1[t]);
        }
    }
    #pragma unroll
    for (int t = 0; t < 7; t++) {
        if (t < nr) {
            size_t g = base + (size_t)rows[t] * DIMN;
            ctx[g + lane]      = __float2bfloat16(c0[t]);
            ctx[g + lane + 32] = __float2bfloat16(c1[t]);
        }
    }
}

// ---------------- launch ------------------------------------------------------
extern "C" void kernel_launch(void* const* d_in, const int* in_sizes, int n_in,
                              void* d_out, int out_size)
{
    const float* Q  = (const float*)d_in[0];
    const float* K  = (const float*)d_in[1];
    const float* V  = (const float*)d_in[2];
    const int*   mask = (const int*)d_in[3];
    const float* Wq = (const float*)d_in[4];
    const float* bq = (const float*)d_in[5];
    const float* Wk = (const float*)d_in[6];
    const float* bk = (const float*)d_in[7];
    const float* Wv = (const float*)d_in[8];
    const float* bv = (const float*)d_in[9];
    const float* Wo = (const float*)d_in[10];
    const float* bo = (const float*)d_in[11];
    const float* ga = (const float*)d_in[12];
    const float* be = (const float*)d_in[13];
    float* out = (float*)d_out;

    __nv_bfloat16 *ln, *proj, *ctx, *wbf;
    cudaGetSymbolAddress((void**)&ln,   g_ln);
    cudaGetSymbolAddress((void**)&proj, g_proj);
    cudaGetSymbolAddress((void**)&ctx,  g_ctx);
    cudaGetSymbolAddress((void**)&wbf,  g_wbf);

    cudaFuncSetAttribute(gemm_bf16<true>,  cudaFuncAttributeMaxDynamicSharedMemorySize, GEMM_SMEM);
    cudaFuncSetAttribute(gemm_bf16<false>, cudaFuncAttributeMaxDynamicSharedMemorySize, GEMM_SMEM);

    size_t seg = (size_t)ROWS * DIMN;
    size_t wseg = (size_t)DIMN * DIMN;

    // fused LN + weight conversion
    prep_kernel<<<3 * ROWS + 4096, 256>>>(Q, K, V, ga, be, ln, Wq, Wk, Wv, Wo, wbf);

    // fused Q/K/V projections (grid.z selects stream), bf16 output
    dim3 gq(DIMN / BN, ROWS / BM, 3);   // (8, 200, 3)
    gemm_bf16<true><<<gq, 256, GEMM_SMEM>>>(ln, wbf, bq, bk, bv, nullptr, nullptr, proj);

    attn_kernel<<<dim3(HEADS, BATCH), 256>>>(proj, proj + seg, proj + 2 * seg, mask, ctx);

    // final projection + bias + residual, fp32 output
    dim3 go(DIMN / BN, ROWS / BM, 1);
    gemm_bf16<false><<<go, 256, GEMM_SMEM>>>(ctx, wbf + 3 * wseg, bo, bo, bo, Q, out, nullptr);
}

// round 17
// speedup vs baseline: 1.2514x; 1.2514x over previous
#include <cuda_runtime.h>
#include <cuda_bf16.h>
#include <mma.h>
#include <cstdint>

using namespace nvcuda;

#define DIMN 1024
#define SEQ 50
#define BATCH 512
#define HEADS 16
#define HD 64
#define ROWS (BATCH*SEQ)   /* 25600 */
#define LN_EPS 1e-5f

// ---------------- scratch (device globals; no allocation allowed) -------------
__device__ __nv_bfloat16 g_ln[3ull * ROWS * DIMN];    // normalized Q,K,V (bf16)
__device__ __nv_bfloat16 g_proj[3ull * ROWS * DIMN];  // projected q,k,v (bf16)
__device__ __nv_bfloat16 g_ctx[(size_t)ROWS * DIMN];  // attention context (bf16)
__device__ __nv_bfloat16 g_wbf[4ull * DIMN * DIMN];   // bf16 weights

// ---------------- cp.async helpers -------------------------------------------
__device__ __forceinline__ uint32_t smem_u32(const void* p) {
    uint32_t a;
    asm("{ .reg .u64 t; cvta.to.shared.u64 t, %1; cvt.u32.u64 %0, t; }" : "=r"(a) : "l"(p));
    return a;
}
#define CP_ASYNC16(dst, src) \
    asm volatile("cp.async.ca.shared.global [%0], [%1], 16;" :: "r"(dst), "l"(src))
#define CP_COMMIT() asm volatile("cp.async.commit_group;" ::: "memory")
#define CP_WAIT1()  asm volatile("cp.async.wait_group 1;" ::: "memory")
#define CP_WAIT0()  asm volatile("cp.async.wait_group 0;" ::: "memory")

// ---------------- prep: LayerNorm (bf16 out) + weight conversion ---------------
__global__ __launch_bounds__(256) void prep_kernel(
    const float* __restrict__ Q, const float* __restrict__ K,
    const float* __restrict__ V, const float* __restrict__ gamma,
    const float* __restrict__ beta, __nv_bfloat16* __restrict__ out,
    const float* __restrict__ Wq, const float* __restrict__ Wk,
    const float* __restrict__ Wv, const float* __restrict__ Wo,
    __nv_bfloat16* __restrict__ wbf)
{
    int blk = blockIdx.x;
    int tid = threadIdx.x;

    if (blk >= 3 * ROWS) {
        int cb = blk - 3 * ROWS;
        int w  = cb >> 10;
        const float* src = (w == 0) ? Wq : (w == 1) ? Wk : (w == 2) ? Wv : Wo;
        __nv_bfloat16* dst = wbf + (size_t)w * DIMN * DIMN;
        size_t i = ((size_t)(cb & 1023) * 256 + tid) * 4;
        float4 v = *(const float4*)(src + i);
        __nv_bfloat162 p0 = {__float2bfloat16(v.x), __float2bfloat16(v.y)};
        __nv_bfloat162 p1 = {__float2bfloat16(v.z), __float2bfloat16(v.w)};
        *(__nv_bfloat162*)(dst + i)     = p0;
        *(__nv_bfloat162*)(dst + i + 2) = p1;
        return;
    }

    int row = blk;
    const float* src;
    if (row < ROWS)            src = Q + (size_t)row * DIMN;
    else if (row < 2 * ROWS)   src = K + (size_t)(row - ROWS) * DIMN;
    else                       src = V + (size_t)(row - 2 * ROWS) * DIMN;
    __nv_bfloat16* dst = out + (size_t)row * DIMN;

    float4 x = *(const float4*)(src + tid * 4);
    float s = x.x + x.y + x.z + x.w;
    float q = x.x * x.x + x.y * x.y + x.z * x.z + x.w * x.w;

    __shared__ float red[2][8];
    #pragma unroll
    for (int o = 16; o; o >>= 1) {
        s += __shfl_xor_sync(0xffffffffu, s, o);
        q += __shfl_xor_sync(0xffffffffu, q, o);
    }
    int warp = tid >> 5, lane = tid & 31;
    if (lane == 0) { red[0][warp] = s; red[1][warp] = q; }
    __syncthreads();
    if (warp == 0) {
        s = (lane < 8) ? red[0][lane] : 0.f;
        q = (lane < 8) ? red[1][lane] : 0.f;
        #pragma unroll
        for (int o = 4; o; o >>= 1) {
            s += __shfl_xor_sync(0xffffffffu, s, o);
            q += __shfl_xor_sync(0xffffffffu, q, o);
        }
        if (lane == 0) { red[0][0] = s; red[1][0] = q; }
    }
    __syncthreads();
    float mean = red[0][0] * (1.0f / DIMN);
    float var  = red[1][0] * (1.0f / DIMN) - mean * mean;
    float inv  = rsqrtf(var + LN_EPS);

    float4 g4 = *(const float4*)(gamma + tid * 4);
    float4 b4 = *(const float4*)(beta + tid * 4);
    __nv_bfloat162 p0 = {__float2bfloat16((x.x - mean) * inv * g4.x + b4.x),
                         __float2bfloat16((x.y - mean) * inv * g4.y + b4.y)};
    __nv_bfloat162 p1 = {__float2bfloat16((x.z - mean) * inv * g4.z + b4.z),
                         __float2bfloat16((x.w - mean) * inv * g4.w + b4.w)};
    *(__nv_bfloat162*)(dst + tid * 4)     = p0;
    *(__nv_bfloat162*)(dst + tid * 4 + 2) = p1;
}

// ---------------- bf16 wmma GEMM (round-11 winner): 256x128, 3-stage -----------
#define BM 256
#define BN 128
#define BK 64
#define APAD 72
#define BPAD 136
#define STG_H (BM*APAD + BK*BPAD)          /* 27136 bf16 = 54272 B */
#define NSTG 3
#define GEMM_SMEM ((NSTG*STG_H*2) > (BM*BN*4) ? (NSTG*STG_H*2) : (BM*BN*4))  /* 162816 */
#define NKT (DIMN/BK)                      /* 16 */

template<bool BF16OUT>
__global__ __launch_bounds__(256, 1) void gemm_bf16(
    const __nv_bfloat16* __restrict__ A0, const __nv_bfloat16* __restrict__ W0,
    const float* __restrict__ b0, const float* __restrict__ b1,
    const float* __restrict__ b2,
    const float* __restrict__ resid,
    float* __restrict__ Cf, __nv_bfloat16* __restrict__ Cb)
{
    extern __shared__ char smraw[];
    __nv_bfloat16* sm = (__nv_bfloat16*)smraw;
    int tid  = threadIdx.x;
    int warp = tid >> 5;
    int wr   = warp >> 1;                  // 0..3 -> M offset wr*64
    int wc   = warp & 1;                   // 0..1 -> N offset wc*64

    int z = blockIdx.z;
    size_t seg  = (size_t)ROWS * DIMN;
    size_t wseg = (size_t)DIMN * DIMN;
    const __nv_bfloat16* A = A0 + z * seg;
    const __nv_bfloat16* W = W0 + z * wseg;
    const float* bias = (z == 0) ? b0 : ((z == 1) ? b1 : b2);

    size_t m0 = (size_t)blockIdx.y * BM;
    int n0 = blockIdx.x * BN;
    const __nv_bfloat16* Ag = A + m0 * DIMN;
    const __nv_bfloat16* Wg = W + n0;

    wmma::fragment<wmma::accumulator, 16, 16, 16, float> cf[4][4];
    #pragma unroll
    for (int i = 0; i < 4; i++)
        #pragma unroll
        for (int j = 0; j < 4; j++)
            wmma::fill_fragment(cf[i][j], 0.0f);

    auto load_stage = [&](int kt, int s) {
        __nv_bfloat16* As = sm + s * STG_H;
        __nv_bfloat16* Bs = As + BM * APAD;
        #pragma unroll
        for (int it = 0; it < 8; it++) {
            int i = tid + it * 256;
            int r = i >> 3, c8 = i & 7;
            CP_ASYNC16(smem_u32(As + r * APAD + c8 * 8),
                       Ag + (size_t)r * DIMN + kt * BK + c8 * 8);
        }
        #pragma unroll
        for (int it = 0; it < 4; it++) {
            int i = tid + it * 256;
            int r = i >> 4, c8 = i & 15;
            CP_ASYNC16(smem_u32(Bs + r * BPAD + c8 * 8),
                       Wg + (size_t)(kt * BK + r) * DIMN + c8 * 8);
        }
        CP_COMMIT();
    };

    load_stage(0, 0);
    load_stage(1, 1);

    for (int kt = 0; kt < NKT; kt++) {
        int s = kt % NSTG;
        if (kt + 1 < NKT) { CP_WAIT1(); } else { CP_WAIT0(); }
        __syncthreads();
        if (kt + 2 < NKT) load_stage(kt + 2, (kt + 2) % NSTG);

        const __nv_bfloat16* As = sm + s * STG_H;
        const __nv_bfloat16* Bs = As + BM * APAD;
        #pragma unroll
        for (int ks = 0; ks < 4; ks++) {
            wmma::fragment<wmma::matrix_a, 16, 16, 16, __nv_bfloat16, wmma::row_major> af[4];
            #pragma unroll
            for (int i = 0; i < 4; i++)
                wmma::load_matrix_sync(af[i], As + (wr * 64 + i * 16) * APAD + ks * 16, APAD);
            #pragma unroll
            for (int j = 0; j < 4; j++) {
                wmma::fragment<wmma::matrix_b, 16, 16, 16, __nv_bfloat16, wmma::row_major> bf;
                wmma::load_matrix_sync(bf, Bs + (ks * 16) * BPAD + wc * 64 + j * 16, BPAD);
                #pragma unroll
                for (int i = 0; i < 4; i++)
                    wmma::mma_sync(cf[i][j], af[i], bf, cf[i][j]);
            }
        }
    }
    __syncthreads();

    float* Cs = (float*)smraw;   // 256*128*4 = 128KB
    #pragma unroll
    for (int i = 0; i < 4; i++)
        #pragma unroll
        for (int j = 0; j < 4; j++)
            wmma::store_matrix_sync(Cs + (wr * 64 + i * 16) * BN + wc * 64 + j * 16,
                                    cf[i][j], BN, wmma::mem_row_major);
    __syncthreads();

    #pragma unroll
    for (int it = 0; it < 32; it++) {
        int i = tid + it * 256;
        int r = i >> 5;
        int c4 = (i & 31) * 4;
        float4 acc = *(float4*)(Cs + r * BN + c4);
        float4 bv  = *(const float4*)(bias + n0 + c4);
        acc.x += bv.x; acc.y += bv.y; acc.z += bv.z; acc.w += bv.w;
        if (BF16OUT) {
            __nv_bfloat16* dst = Cb + z * seg + (m0 + r) * DIMN + n0 + c4;
            __nv_bfloat162 p0 = {__float2bfloat16(acc.x), __float2bfloat16(acc.y)};
            __nv_bfloat162 p1 = {__float2bfloat16(acc.z), __float2bfloat16(acc.w)};
            *(__nv_bfloat162*)(dst)     = p0;
            *(__nv_bfloat162*)(dst + 2) = p1;
        } else {
            float4 rv = *(const float4*)(resid + (m0 + r) * DIMN + n0 + c4);
            acc.x += rv.x; acc.y += rv.y; acc.z += rv.z; acc.w += rv.w;
            *(float4*)(Cf + (m0 + r) * DIMN + n0 + c4) = acc;
        }
    }
}

// ---------------- Attention via wmma: one block per (batch, head) --------------
// SEQ padded 50->64. S = Q@K^T (bf16 MMA, fp32 acc), fp32 softmax+mask,
// P (bf16, reuses Q smem) @ V. Rows >=50 never written out; P cols >=50 = 0.
#define QPAD 72    // bf16 row stride (144B)
#define SPAD 68    // fp32 row stride (multiple of 4)

__global__ __launch_bounds__(128) void attn_kernel(
    const __nv_bfloat16* __restrict__ qp, const __nv_bfloat16* __restrict__ kp,
    const __nv_bfloat16* __restrict__ vp, const int* __restrict__ mask,
    __nv_bfloat16* __restrict__ ctx)
{
    __shared__ __align__(16) __nv_bfloat16 sq[64 * QPAD];   // Q, later P (aliased)
    __shared__ __align__(16) __nv_bfloat16 sk[64 * QPAD];
    __shared__ __align__(16) __nv_bfloat16 sv[64 * QPAD];
    __shared__ __align__(16) float         ss[64 * SPAD];   // S, later ctx

    int h = blockIdx.x, b = blockIdx.y;
    int tid = threadIdx.x, warp = tid >> 5, lane = tid & 31;
    size_t base = ((size_t)b * SEQ) * DIMN + (size_t)h * HD;

    // load q,k,v rows [0,50): 16B (8 bf16) per thread-iteration
    for (int i2 = tid; i2 < SEQ * 8; i2 += 128) {
        int s = i2 >> 3, d8 = (i2 & 7) * 8;
        size_t g = base + (size_t)s * DIMN + d8;
        *(uint4*)(sq + s * QPAD + d8) = *(const uint4*)(qp + g);
        *(uint4*)(sk + s * QPAD + d8) = *(const uint4*)(kp + g);
        *(uint4*)(sv + s * QPAD + d8) = *(const uint4*)(vp + g);
    }
    // zero pad rows [50,64) of K and V (S cols >=50 become 0; V pad inert)
    const __nv_bfloat16 Z = __float2bfloat16(0.f);
    for (int i = tid; i < 14 * 64; i += 128) {
        int r = 50 + (i >> 6), d = i & 63;
        sk[r * QPAD + d] = Z;
        sv[r * QPAD + d] = Z;
    }
    __syncthreads();

    // ---- S = Q @ K^T : warp computes rows [warp*16, warp*16+16), all 64 cols
    {
        wmma::fragment<wmma::accumulator, 16, 16, 16, float> cs[4];
        #pragma unroll
        for (int j = 0; j < 4; j++) wmma::fill_fragment(cs[j], 0.0f);
        #pragma unroll
        for (int ks = 0; ks < 4; ks++) {
            wmma::fragment<wmma::matrix_a, 16, 16, 16, __nv_bfloat16, wmma::row_major> af;
            wmma::load_matrix_sync(af, sq + (warp * 16) * QPAD + ks * 16, QPAD);
            #pragma unroll
            for (int jt = 0; jt < 4; jt++) {
                // K^T as col_major view of row-major K: B[k][j] = sk[j*QPAD + k]
                wmma::fragment<wmma::matrix_b, 16, 16, 16, __nv_bfloat16, wmma::col_major> bf;
                wmma::load_matrix_sync(bf, sk + (jt * 16) * QPAD + ks * 16, QPAD);
                wmma::mma_sync(cs[jt], af, bf, cs[jt]);
            }
        }
        #pragma unroll
        for (int jt = 0; jt < 4; jt++)
            wmma::store_matrix_sync(ss + (warp * 16) * SPAD + jt * 16, cs[jt],
                                    SPAD, wmma::mem_row_major);
    }
    __syncthreads();

    // ---- softmax (fp32) + mask; write P (bf16) into sq (Q is dead) ----
    const int* mrow = mask + (size_t)b * SEQ * SEQ;
    __nv_bfloat16* sp = sq;
    const float NEGINF = __int_as_float(0xff800000);
    for (int r = warp; r < SEQ; r += 4) {
        int j1 = lane + 32;
        bool v1 = j1 < SEQ;
        float s0 = ss[r * SPAD + lane] * 0.125f;
        if (mrow[r * SEQ + lane]) s0 = NEGINF;
        float s1 = NEGINF;
        if (v1 && !mrow[r * SEQ + j1]) s1 = ss[r * SPAD + j1] * 0.125f;
        float m = fmaxf(s0, s1);
        #pragma unroll
        for (int o = 16; o; o >>= 1) m = fmaxf(m, __shfl_xor_sync(0xffffffffu, m, o));
        float e0 = __expf(s0 - m);
        float e1 = v1 ? __expf(s1 - m) : 0.f;
        float sum = e0 + e1;
        #pragma unroll
        for (int o = 16; o; o >>= 1) sum += __shfl_xor_sync(0xffffffffu, sum, o);
        float inv = 1.0f / sum;
        sp[r * QPAD + lane] = __float2bfloat16(e0 * inv);
        sp[r * QPAD + j1]   = __float2bfloat16(v1 ? e1 * inv : 0.f);  // cols 50..63 -> 0
    }
    __syncthreads();

    // ---- ctx = P @ V : warp computes rows [warp*16, +16), 64 d-cols ----
    {
        wmma::fragment<wmma::accumulator, 16, 16, 16, float> cc[4];
        #pragma unroll
        for (int j = 0; j < 4; j++) wmma::fill_fragment(cc[j], 0.0f);
        #pragma unroll
        for (int ks = 0; ks < 4; ks++) {
            wmma::fragment<wmma::matrix_a, 16, 16, 16, __nv_bfloat16, wmma::row_major> af;
            wmma::load_matrix_sync(af, sp + (warp * 16) * QPAD + ks * 16, QPAD);
            #pragma unroll
            for (int dt = 0; dt < 4; dt++) {
                wmma::fragment<wmma::matrix_b, 16, 16, 16, __nv_bfloat16, wmma::row_major> bf;
                wmma::load_matrix_sync(bf, sv + (ks * 16) * QPAD + dt * 16, QPAD);
                wmma::mma_sync(cc[dt], af, bf, cc[dt]);
            }
        }
        __syncthreads();   // ss free (softmax done)
        #pragma unroll
        for (int dt = 0; dt < 4; dt++)
            wmma::store_matrix_sync(ss + (warp * 16) * SPAD + dt * 16, cc[dt],
                                    SPAD, wmma::mem_row_major);
    }
    __syncthreads();

    // ---- write rows [0,50) as bf16 ----
    for (int i2 = tid; i2 < SEQ * 32; i2 += 128) {
        int s = i2 >> 5, d2 = (i2 & 31) * 2;
        __nv_bfloat162 p = {__float2bfloat16(ss[s * SPAD + d2]),
                            __float2bfloat16(ss[s * SPAD + d2 + 1])};
        *(__nv_bfloat162*)(ctx + base + (size_t)s * DIMN + d2) = p;
    }
}

// ---------------- launch ------------------------------------------------------
extern "C" void kernel_launch(void* const* d_in, const int* in_sizes, int n_in,
                              void* d_out, int out_size)
{
    const float* Q  = (const float*)d_in[0];
    const float* K  = (const float*)d_in[1];
    const float* V  = (const float*)d_in[2];
    const int*   mask = (const int*)d_in[3];
    const float* Wq = (const float*)d_in[4];
    const float* bq = (const float*)d_in[5];
    const float* Wk = (const float*)d_in[6];
    const float* bk = (const float*)d_in[7];
    const float* Wv = (const float*)d_in[8];
    const float* bv = (const float*)d_in[9];
    const float* Wo = (const float*)d_in[10];
    const float* bo = (const float*)d_in[11];
    const float* ga = (const float*)d_in[12];
    const float* be = (const float*)d_in[13];
    float* out = (float*)d_out;

    __nv_bfloat16 *ln, *proj, *ctx, *wbf;
    cudaGetSymbolAddress((void**)&ln,   g_ln);
    cudaGetSymbolAddress((void**)&proj, g_proj);
    cudaGetSymbolAddress((void**)&ctx,  g_ctx);
    cudaGetSymbolAddress((void**)&wbf,  g_wbf);

    cudaFuncSetAttribute(gemm_bf16<true>,  cudaFuncAttributeMaxDynamicSharedMemorySize, GEMM_SMEM);
    cudaFuncSetAttribute(gemm_bf16<false>, cudaFuncAttributeMaxDynamicSharedMemorySize, GEMM_SMEM);

    size_t seg = (size_t)ROWS * DIMN;
    size_t wseg = (size_t)DIMN * DIMN;

    // fused LN + weight conversion
    prep_kernel<<<3 * ROWS + 4096, 256>>>(Q, K, V, ga, be, ln, Wq, Wk, Wv, Wo, wbf);

    // fused Q/K/V projections (grid.z selects stream), bf16 output
    dim3 gq(DIMN / BN, ROWS / BM, 3);   // (8, 100, 3)
    gemm_bf16<true><<<gq, 256, GEMM_SMEM>>>(ln, wbf, bq, bk, bv, nullptr, nullptr, proj);

    attn_kernel<<<dim3(HEADS, BATCH), 128>>>(proj, proj + seg, proj + 2 * seg, mask, ctx);

    // final projection + bias + residual, fp32 output
    dim3 go(DIMN / BN, ROWS / BM, 1);
    gemm_bf16<false><<<go, 256, GEMM_SMEM>>>(ctx, wbf + 3 * wseg, bo, bo, bo, Q, out, nullptr);
}